// round 1
// baseline (speedup 1.0000x reference)
#include <cuda_runtime.h>

#define BB   16384
#define FF   30
#define BINS 30
#define EMB  100
#define NROW (BB*FF)        // 491520

// exp2 coefficients per sign branch: [0] = x>0, [1] = x<0
__device__ float g_d[2][32];

// ---------------------------------------------------------------------------
// Precompute kernel: collapse W1/Wl into two 30-vectors of exp2 coefficients.
// ---------------------------------------------------------------------------
__global__ void precompute_kernel(const float* __restrict__ W1,
                                  const float* __restrict__ Wl) {
    __shared__ float vs[2][32];
    __shared__ float us[2][32];
    int t = threadIdx.x;       // 64 threads
    int s = t >> 5;            // 0: x>0 branch, 1: x<0 branch
    int o = t & 31;

    float v = 0.f;
    if (o < BINS) {
        float w = W1[o];
        // x>0: x*w > 0 iff w > 0 ; x<0: x*w > 0 iff w < 0
        bool act = (s == 0) ? (w > 0.f) : (w < 0.f);
        v = act ? w : 0.01f * w;
    }
    vs[s][o] = v;
    __syncthreads();

    float u = 0.f;
    if (o < BINS) {
        #pragma unroll
        for (int i = 0; i < BINS; i++) u += Wl[o * BINS + i] * vs[s][i];
        u += 0.1f * v;
    }
    us[s][o] = u;
    __syncthreads();

    float dval = 0.f;
    if (o < BINS) {
        // extreme so that x * (u - ext) <= 0 always
        float ext = us[s][0];
        #pragma unroll
        for (int i = 1; i < BINS; i++) {
            float z = us[s][i];
            ext = (s == 0) ? fmaxf(ext, z) : fminf(ext, z);
        }
        const float T_LOG2E = 0.5f * 1.44269504088896340736f;  // T * log2(e)
        dval = T_LOG2E * (u - ext);
    }
    g_d[s][o] = dval;
}

// ---------------------------------------------------------------------------
// Main kernel: one thread per (b,f) element.
//   p_o = exp2(x * d_s[o]);  out_e = (sum_o p_o * W2[e,o]) / Z
// W2 held transposed in shared so the inner loads are float4 + warp-uniform.
// ---------------------------------------------------------------------------
__global__ void __launch_bounds__(256)
main_kernel(const float* __restrict__ x,
            const float* __restrict__ W2,
            float* __restrict__ out) {
    __shared__ float w2t[BINS][EMB];   // [o][e], rows 400B (16B aligned)
    __shared__ float dsh[2][32];

    int tid = threadIdx.x;
    for (int i = tid; i < EMB * BINS; i += 256) {
        int e = i / BINS, o = i % BINS;
        w2t[o][e] = W2[i];
    }
    if (tid < 64) dsh[tid >> 5][tid & 31] = g_d[tid >> 5][tid & 31];
    __syncthreads();

    int idx = blockIdx.x * 256 + tid;          // grid sized exactly
    float xv = x[idx];
    const float* d = (xv > 0.f) ? dsh[0] : dsh[1];

    float p[BINS];
    float Z = 0.f;
    #pragma unroll
    for (int o = 0; o < BINS; o++) {
        float a = xv * d[o];
        float e;
        asm("ex2.approx.ftz.f32 %0, %1;" : "=f"(e) : "f"(a));
        p[o] = e;
        Z += e;
    }
    float invZ = 1.0f / Z;

    float* orow = out + (size_t)idx * EMB;
    #pragma unroll 5
    for (int ec = 0; ec < EMB; ec += 4) {
        float ax = 0.f, ay = 0.f, az = 0.f, aw = 0.f;
        #pragma unroll
        for (int o = 0; o < BINS; o++) {
            float4 w = *reinterpret_cast<const float4*>(&w2t[o][ec]);
            float po = p[o];
            ax = fmaf(po, w.x, ax);
            ay = fmaf(po, w.y, ay);
            az = fmaf(po, w.z, az);
            aw = fmaf(po, w.w, aw);
        }
        float4 r;
        r.x = ax * invZ; r.y = ay * invZ; r.z = az * invZ; r.w = aw * invZ;
        *reinterpret_cast<float4*>(&orow[ec]) = r;
    }
}

// ---------------------------------------------------------------------------
extern "C" void kernel_launch(void* const* d_in, const int* in_sizes, int n_in,
                              void* d_out, int out_size) {
    const float* x  = (const float*)d_in[0];   // (16384, 1, 30)
    const float* W1 = (const float*)d_in[1];   // (30, 1)
    const float* Wl = (const float*)d_in[2];   // (30, 30)
    const float* W2 = (const float*)d_in[3];   // (100, 30)
    float* out = (float*)d_out;                // (16384, 3000)

    precompute_kernel<<<1, 64>>>(W1, Wl);
    main_kernel<<<NROW / 256, 256>>>(x, W2, out);
}